// round 3
// baseline (speedup 1.0000x reference)
#include <cuda_runtime.h>
#include <math.h>

#ifndef M_PI
#define M_PI 3.14159265358979323846
#endif

#define WPC 4                 // warps per CTA
#define FULLMASK 0xffffffffu
#define EPSV 1e-6f

// ---------------- warp reduction helpers ----------------
__device__ __forceinline__ float wredsum(float x){
#pragma unroll
  for (int m = 16; m > 0; m >>= 1) x += __shfl_xor_sync(FULLMASK, x, m);
  return x;
}
__device__ __forceinline__ float wredmax(float x){
#pragma unroll
  for (int m = 16; m > 0; m >>= 1) x = fmaxf(x, __shfl_xor_sync(FULLMASK, x, m));
  return x;
}
__device__ __forceinline__ int wredmini(int x){
#pragma unroll
  for (int m = 16; m > 0; m >>= 1){ int o = __shfl_xor_sync(FULLMASK, x, m); x = (o < x) ? o : x; }
  return x;
}

// ---------------- warp bitonic sort of 256 floats (8 regs/lane, idx i = lane*8 + r) ----------------
__device__ __forceinline__ void ce(float &a, float &b, bool up){
  float mn = fminf(a,b), mx = fmaxf(a,b);
  a = up ? mn : mx;  b = up ? mx : mn;
}
__device__ __forceinline__ void ce_shfl(float v[8], int jl, bool up, int lane){
  bool keepmin = (((lane & jl) == 0) == up);
#pragma unroll
  for (int r = 0; r < 8; r++){
    float o = __shfl_xor_sync(FULLMASK, v[r], jl);
    float mn = fminf(v[r], o), mx = fmaxf(v[r], o);
    v[r] = keepmin ? mn : mx;
  }
}
__device__ __forceinline__ void merge8(float v[8], bool up){
  ce(v[0],v[4],up); ce(v[1],v[5],up); ce(v[2],v[6],up); ce(v[3],v[7],up);
  ce(v[0],v[2],up); ce(v[1],v[3],up); ce(v[4],v[6],up); ce(v[5],v[7],up);
  ce(v[0],v[1],up); ce(v[2],v[3],up); ce(v[4],v[5],up); ce(v[6],v[7],up);
}
__device__ __forceinline__ void sort256(float v[8], int lane){
  // k=2
  ce(v[0],v[1],true);  ce(v[2],v[3],false); ce(v[4],v[5],true);  ce(v[6],v[7],false);
  // k=4
  ce(v[0],v[2],true);  ce(v[1],v[3],true);  ce(v[4],v[6],false); ce(v[5],v[7],false);
  ce(v[0],v[1],true);  ce(v[2],v[3],true);  ce(v[4],v[5],false); ce(v[6],v[7],false);
  // k=8
  { bool up = ((lane & 1) == 0); merge8(v, up); }
  // k=16
  { bool up = ((lane & 2) == 0); ce_shfl(v,1,up,lane); merge8(v, up); }
  // k=32
  { bool up = ((lane & 4) == 0); ce_shfl(v,2,up,lane); ce_shfl(v,1,up,lane); merge8(v, up); }
  // k=64
  { bool up = ((lane & 8) == 0); ce_shfl(v,4,up,lane); ce_shfl(v,2,up,lane); ce_shfl(v,1,up,lane); merge8(v, up); }
  // k=128
  { bool up = ((lane & 16) == 0); ce_shfl(v,8,up,lane); ce_shfl(v,4,up,lane); ce_shfl(v,2,up,lane); ce_shfl(v,1,up,lane); merge8(v, up); }
  // k=256 (all ascending)
  { ce_shfl(v,16,true,lane); ce_shfl(v,8,true,lane); ce_shfl(v,4,true,lane); ce_shfl(v,2,true,lane); ce_shfl(v,1,true,lane); merge8(v, true); }
}
template<int G> __device__ __forceinline__ float rank_of(const float v[8]){
  return __shfl_sync(FULLMASK, v[G & 7], G >> 3);
}

// ---------------- summary stats (8 features) for a nonnegative signal in regs ----------------
__device__ void do_summary(float n[8], float *featbase, int lane){
  float s = 0.f, s2 = 0.f, mx = 0.f;
#pragma unroll
  for (int r = 0; r < 8; r++){ s += n[r]; s2 += n[r]*n[r]; mx = fmaxf(mx, n[r]); }
  s  = wredsum(s); s2 = wredsum(s2); mx = wredmax(mx);
  float mean = s * (1.f/256.f);
  float m2 = 0.f, m3 = 0.f, m4 = 0.f;
#pragma unroll
  for (int r = 0; r < 8; r++){
    float c = n[r] - mean; float c2 = c*c;
    m2 += c2; m3 += c2*c; m4 += c2*c2;
  }
  m2 = wredsum(m2); m3 = wredsum(m3); m4 = wredsum(m4);
  sort256(n, lane);
  float s63  = rank_of<63>(n),  s64  = rank_of<64>(n);
  float s191 = rank_of<191>(n), s192 = rank_of<192>(n);
  float s242 = rank_of<242>(n), s243 = rank_of<243>(n);
  float q25 = 0.25f*s63 + 0.75f*s64;
  float q75 = 0.75f*s191 + 0.25f*s192;
  float q95 = 0.75f*s242 + 0.25f*s243;
  float var_pop = m2 * (1.f/256.f);
  float var = fmaxf(var_pop, EPSV);
  float stdv = sqrtf(m2 * (1.f/255.f));
  float rms  = sqrtf(s2 * (1.f/256.f));
  float skew = fminf(fmaxf((m3 * (1.f/256.f)) / (var * sqrtf(var)), -10.f), 10.f);
  float kurt = fminf(fmaxf((m4 * (1.f/256.f)) / (var * var), 0.f), 30.f);
  if (lane == 0){
    featbase[0] = mean; featbase[1] = stdv; featbase[2] = rms; featbase[3] = mx;
    featbase[4] = q95;  featbase[5] = q75 - q25; featbase[6] = skew; featbase[7] = kurt;
  }
}

// ---------------- phase features ----------------
__device__ void do_phase(const float *z, int off, int sT, int R, float *feat6, int lane){
  float mx = 0.f;
  for (int t = lane; t < sT; t += 32) mx = fmaxf(mx, fabsf(z[off + t]));
  mx = wredmax(mx);
  int idx = 1 << 30;
  for (int t = lane; t < sT; t += 32) if (fabsf(z[off + t]) == mx) idx = (t < idx) ? t : idx;
  idx = wredmini(idx);
  float pk = mx;
  int W = 2*R + 1;
  float ssum = 0.f, spre = 0.f, spost = 0.f, cnt = 0.f;
  for (int j = lane; j < W; j += 32){
    int u = idx + j - R; u = max(0, min(u, sT - 1));
    float loc = fabsf(z[off + u]);
    ssum += loc;
    if (j < R) spre += loc;
    if (j > R) spost += loc;
    if (loc >= 0.2f * pk) cnt += 1.f;
  }
  ssum = wredsum(ssum); spre = wredsum(spre); spost = wredsum(spost); cnt = wredsum(cnt);
  float mj = 0.f, sj2 = 0.f;
  for (int t = lane; t < sT - 1; t += 32){
    float d = z[off + t + 1] - z[off + t];
    mj = fmaxf(mj, fabsf(d)); sj2 += d*d;
  }
  mj = wredmax(mj); sj2 = wredsum(sj2);
  if (lane == 0){
    feat6[0] = pk;
    feat6[1] = ssum;
    feat6[2] = (spost / (float)R) / ((spre / (float)R) + EPSV);
    feat6[3] = cnt / (float)W;
    feat6[4] = mj;
    feat6[5] = sqrtf(sj2 / (float)(sT - 1));
  }
}

// ---------------- spectral features from power[0..128] ----------------
__device__ void do_spectral(const float *pw, float *feat7, int lane){
  float tot=0.f, b0=0.f, b1=0.f, b2=0.f, b3=0.f, b4=0.f;
  for (int k = lane; k <= 128; k += 32){
    float p = pw[k]; tot += p;
    if (k < 8) b0 += p; else if (k < 16) b1 += p; else if (k < 26) b2 += p;
    else if (k < 52) b3 += p; else if (k < 103) b4 += p;
  }
  tot = wredsum(tot); b0 = wredsum(b0); b1 = wredsum(b1);
  b2 = wredsum(b2);  b3 = wredsum(b3); b4 = wredsum(b4);
  tot = fmaxf(tot, 1e-8f);
  float inv = 1.f / tot;
  float ent = 0.f;
  for (int k = lane; k <= 128; k += 32){
    float p = fmaxf(pw[k] * inv, 1e-8f);
    ent += p * logf(p);
  }
  ent = wredsum(ent);
  // spectral edge: first k where cumsum(p) >= 0.85
  float carry = 0.f; int found = 200;
  for (int c = 0; c < 5; c++){
    int k = c*32 + lane;
    float p = (k <= 128) ? fmaxf(pw[k] * inv, 1e-8f) : 0.f;
    float s = p;
#pragma unroll
    for (int o = 1; o < 32; o <<= 1){
      float u = __shfl_up_sync(FULLMASK, s, o);
      if (lane >= o) s += u;
    }
    float cum = carry + s;
    bool pred = (k <= 128) && (cum >= 0.85f);
    unsigned mball = __ballot_sync(FULLMASK, pred);
    if (mball && found == 200) found = c*32 + __ffs(mball) - 1;
    carry += __shfl_sync(FULLMASK, s, 31);
  }
  int eidx = (found == 200) ? 0 : found;
  if (lane == 0){
    feat7[0] = b0*inv; feat7[1] = b1*inv; feat7[2] = b2*inv; feat7[3] = b3*inv; feat7[4] = b4*inv;
    feat7[5] = -ent / 4.867534450455582f;   // log(130)
    feat7[6] = (float)eidx * 0.390625f;     // k * 100/256
  }
}

// ---------------- time-domain normalized xcorr, lags -8..8 ----------------
__device__ void do_xcorr(const float *zx, const float *zy, float &mv, float &lag, int lane){
  float sx = 0.f, sy = 0.f;
  for (int t = lane; t < 256; t += 32){ sx += zx[t]; sy += zy[t]; }
  sx = wredsum(sx) * (1.f/256.f); sy = wredsum(sy) * (1.f/256.f);
  float g[17];
#pragma unroll
  for (int j = 0; j < 17; j++) g[j] = 0.f;
  float sx2 = 0.f, sy2 = 0.f;
  for (int t = lane; t < 256; t += 32){
    float x0 = zx[t] - sx; sx2 += x0*x0;
    float yc = zy[t] - sy; sy2 += yc*yc;
#pragma unroll
    for (int mm = -8; mm <= 8; mm++){
      int u = t - mm;
      if (u >= 0 && u < 256) g[mm + 8] += x0 * (zy[u] - sy);
    }
  }
  sx2 = wredsum(sx2); sy2 = wredsum(sy2);
#pragma unroll
  for (int j = 0; j < 17; j++) g[j] = wredsum(g[j]);
  float denom = sqrtf(sx2) * sqrtf(sy2) + EPSV;
  float best = -1e30f; int bi = 0;
#pragma unroll
  for (int j = 0; j < 17; j++){
    float v = g[j] / denom;
    if (v > best){ best = v; bi = j; }
  }
  mv = best; lag = (float)(bi - 8);
}

// ---------------- warp FFT-256 (DIF, bit-reversed output) ----------------
__device__ void fft256(float *re, float *im, const float *twre, const float *twim, int lane){
#pragma unroll
  for (int half = 128; half >= 1; half >>= 1){
    int step = 128 / half;
    __syncwarp();
#pragma unroll
    for (int q4 = 0; q4 < 4; q4++){
      int q   = lane + 32*q4;
      int blk = q / half;
      int jj  = q - blk*half;
      int i   = blk*(half << 1) + jj;
      int ip  = i + half;
      float ar = re[i],  ai = im[i];
      float br = re[ip], bi = im[ip];
      float wr = twre[jj*step], wi = twim[jj*step];
      re[i] = ar + br;  im[i] = ai + bi;
      float tr = ar - br, ti = ai - bi;
      re[ip] = tr*wr - ti*wi;
      im[ip] = tr*wi + ti*wr;
    }
  }
  __syncwarp();
}

__device__ __forceinline__ void load8(const float *rowbase, int lane, float v[8]){
  const float4 *p = reinterpret_cast<const float4*>(rowbase) + lane*2;
  float4 a = p[0], b = p[1];
  v[0]=a.x; v[1]=a.y; v[2]=a.z; v[3]=a.w; v[4]=b.x; v[5]=b.y; v[6]=b.z; v[7]=b.w;
}

__global__ void __launch_bounds__(WPC*32)
terrain_kernel(const float* __restrict__ foot, const float* __restrict__ shank,
               const float* __restrict__ thigh, float* __restrict__ out, int B)
{
  __shared__ float twre[128], twim[128];
  __shared__ float zsh_s[WPC][4*256];
  __shared__ float fre_s[WPC][256], fim_s[WPC][256];
  __shared__ float pw_s[WPC][4*132];
  __shared__ float feat_s[WPC][224];
  __shared__ float wz_s[WPC][4];

  int tid = threadIdx.x;
  if (tid < 128){
    float sv, cv;
    sincosf((float)(-2.0 * M_PI / 256.0) * (float)tid, &sv, &cv);
    twre[tid] = cv;
    twim[tid] = sv;
  }
  __syncthreads();

  int lane = tid & 31, w = tid >> 5;
  int b = blockIdx.x * WPC + w;
  if (b >= B) return;

  float *Z    = zsh_s[w];
  float *FRE  = fre_s[w];
  float *FIM  = fim_s[w];
  float *PW   = pw_s[w];
  float *FEAT = feat_s[w];
  float *WZ   = wz_s[w];

  const float *F  = foot  + (size_t)b * 3072;
  const float *S  = shank + (size_t)b * 3072;
  const float *TH = thigh + (size_t)b * 3072;

  const int chmap[4] = {0, 6, 3, 9};   // a_lt, a_rt, g_lt, g_rt

  // ---- 12 norm signals: summary stats + z staging + horizontal blocks ----
  for (int s = 0; s < 12; s++){
    const float *base = (s < 4) ? F : (s < 8) ? S : TH;
    const float *row = base + chmap[s & 3] * 256;
    float x0[8], x1[8], x2[8];
    load8(row,        lane, x0);
    load8(row + 256,  lane, x1);
    load8(row + 512,  lane, x2);

    if (s == 0 || s == 1 || s == 4 || s == 5){
      int zi = (s < 2) ? s : (s - 2);
#pragma unroll
      for (int r = 0; r < 8; r++) Z[zi*256 + lane*8 + r] = x2[r];
      float zm = 0.f;
#pragma unroll
      for (int r = 0; r < 8; r++) zm = fmaxf(zm, fabsf(x2[r]));
      zm = wredmax(zm);
      if (lane == 0) WZ[zi] = zm;
    }

    if (s == 0 || s == 1){
      // horizontal-plane block (xy magnitude of channels ch, ch+1; z = ch+2)
      float h[8];
#pragma unroll
      for (int r = 0; r < 8; r++) h[r] = sqrtf(x0[r]*x0[r] + x1[r]*x1[r]);
      float sh2 = 0.f, hmax = 0.f, absz = 0.f;
#pragma unroll
      for (int r = 0; r < 8; r++){ sh2 += h[r]*h[r]; hmax = fmaxf(hmax, h[r]); absz += fabsf(x2[r]); }
      sh2 = wredsum(sh2); hmax = wredmax(hmax); absz = wredsum(absz);
      float h0n = __shfl_down_sync(FULLMASK, h[0], 1);   // lane+1's h[0]
      float mj = 0.f, sj2 = 0.f;
#pragma unroll
      for (int r = 0; r < 8; r++){
        float nxt = (r < 7) ? h[r+1] : h0n;
        bool valid = (lane*8 + r) < 255;
        float d = nxt - h[r];
        if (valid){ mj = fmaxf(mj, fabsf(d)); sj2 += d*d; }
      }
      mj = wredmax(mj); sj2 = wredsum(sj2);
      sort256(h, lane);
      float q95h = 0.75f * rank_of<242>(h) + 0.25f * rank_of<243>(h);
      float rmsh  = sqrtf(sh2 * (1.f/256.f));
      float meanz = absz * (1.f/256.f);
      if (lane == 0){
        float *fb = FEAT + 184 + s*6;
        fb[0] = rmsh; fb[1] = hmax; fb[2] = q95h;
        fb[3] = mj;   fb[4] = sqrtf(sj2 * (1.f/255.f));
        fb[5] = rmsh / (meanz + EPSV);
      }
    }

    float n[8];
#pragma unroll
    for (int r = 0; r < 8; r++) n[r] = sqrtf(x0[r]*x0[r] + x1[r]*x1[r] + x2[r]*x2[r]);
    do_summary(n, FEAT + s*8, lane);
  }
  __syncwarp();

  // ---- spectral: 2 complex FFTs serve 4 real z signals ----
  for (int f = 0; f < 2; f++){
    for (int t = lane; t < 256; t += 32){
      FRE[t] = Z[(2*f + 0)*256 + t];
      FIM[t] = Z[(2*f + 1)*256 + t];
    }
    __syncwarp();
    fft256(FRE, FIM, twre, twim, lane);
    for (int k = lane; k <= 128; k += 32){
      int kk = (256 - k) & 255;
      int p1 = __brev((unsigned)k)  >> 24;
      int p2 = __brev((unsigned)kk) >> 24;
      float a = FRE[p1], bb = FIM[p1], c = FRE[p2], d = FIM[p2];
      float xr = 0.5f*(a + c),  xi = 0.5f*(bb - d);
      float yr = 0.5f*(bb + d), yi = 0.5f*(c - a);
      PW[(2*f + 0)*132 + k] = xr*xr + xi*xi;
      PW[(2*f + 1)*132 + k] = yr*yr + yi*yi;
    }
    __syncwarp();
  }
  for (int z = 0; z < 4; z++)
    do_spectral(PW + z*132, FEAT + 96 + z*7, lane);

  // ---- phase features: heel + toe per z ----
  for (int z = 0; z < 4; z++){
    do_phase(Z + z*256, 0,   115, 19, FEAT + 124 + z*6, lane);
    do_phase(Z + z*256, 153, 103, 17, FEAT + 148 + z*6, lane);
  }

  // ---- per-side blocks (xcorr + ratios) ----
  for (int side = 0; side < 2; side++){
    int fi = side, si = side + 2;
    float mv, lagv;
    do_xcorr(Z + fi*256, Z + si*256, mv, lagv, lane);
    if (lane == 0){
      float ratio = FEAT[(4 + side)*8 + 2] / (FEAT[side*8 + 2] + EPSV);
      float *fb = FEAT + 172 + side*6;
      fb[0] = WZ[si] / (WZ[fi] + EPSV);
      fb[1] = ratio;
      fb[2] = FEAT[124 + si*6 + 1] / (FEAT[124 + fi*6 + 1] + EPSV);
      fb[3] = mv;
      fb[4] = lagv;
      fb[5] = 0.5f * (FEAT[96 + si*7 + 4] / (FEAT[96 + fi*7 + 4] + EPSV) + (1.f - ratio));
    }
  }

  // ---- asymmetry block ----
  if (lane == 0){
    float *fb = FEAT + 196;
    #define ASYM(a_, b_) fabsf(logf(((a_) + EPSV) / ((b_) + EPSV)))
    fb[0]  = ASYM(FEAT[0*8+3],  FEAT[1*8+3]);
    fb[1]  = ASYM(FEAT[0*8+2],  FEAT[1*8+2]);
    fb[2]  = ASYM(FEAT[2*8+3],  FEAT[3*8+3]);
    fb[3]  = ASYM(FEAT[2*8+2],  FEAT[3*8+2]);
    fb[4]  = ASYM(FEAT[4*8+3],  FEAT[5*8+3]);
    fb[5]  = ASYM(FEAT[4*8+2],  FEAT[5*8+2]);
    fb[6]  = ASYM(FEAT[6*8+3],  FEAT[7*8+3]);
    fb[7]  = ASYM(FEAT[6*8+2],  FEAT[7*8+2]);
    fb[8]  = ASYM(FEAT[8*8+2],  FEAT[9*8+2]);
    fb[9]  = ASYM(FEAT[10*8+2], FEAT[11*8+2]);
    fb[10] = ASYM(FEAT[124+0*6+1], FEAT[124+1*6+1]);
    fb[11] = ASYM(FEAT[124+2*6+1], FEAT[124+3*6+1]);
    #undef ASYM
  }
  __syncwarp();

  // ---- write 208 features for this batch ----
  float *ob = out + (size_t)b * 208;
  for (int i = lane; i < 208; i += 32) ob[i] = FEAT[i];
}

extern "C" void kernel_launch(void* const* d_in, const int* in_sizes, int n_in,
                              void* d_out, int out_size) {
  const float* foot  = (const float*)d_in[0];
  const float* shank = (const float*)d_in[1];
  const float* thigh = (const float*)d_in[2];
  float* out = (float*)d_out;
  int B = in_sizes[0] / (12 * 256);
  int ctas = (B + WPC - 1) / WPC;
  terrain_kernel<<<ctas, WPC*32>>>(foot, shank, thigh, out, B);
}

// round 9
// speedup vs baseline: 1.8225x; 1.8225x over previous
#include <cuda_runtime.h>
#include <math.h>

#ifndef M_PI
#define M_PI 3.14159265358979323846
#endif

#define WPC 4                 // warps per CTA
#define FULLMASK 0xffffffffu
#define EPSV 1e-6f

// ---------------- approx-math helpers (accuracy ~2^-20, tolerance is 1e-3) ----------------
__device__ __forceinline__ float fsqrt_a(float x){ float r; asm("sqrt.approx.f32 %0, %1;" : "=f"(r) : "f"(x)); return r; }
__device__ __forceinline__ float frcp_a(float x){ float r; asm("rcp.approx.f32 %0, %1;" : "=f"(r) : "f"(x)); return r; }

// ---------------- warp reduction helpers ----------------
__device__ __forceinline__ float wredsum(float x){
#pragma unroll
  for (int m = 16; m > 0; m >>= 1) x += __shfl_xor_sync(FULLMASK, x, m);
  return x;
}
__device__ __forceinline__ float wredmax(float x){
#pragma unroll
  for (int m = 16; m > 0; m >>= 1) x = fmaxf(x, __shfl_xor_sync(FULLMASK, x, m));
  return x;
}
// joint (max value, min index on ties) reduction
__device__ __forceinline__ void wredmaxidx(float &mx, int &idx){
#pragma unroll
  for (int m = 16; m > 0; m >>= 1){
    float omx = __shfl_xor_sync(FULLMASK, mx, m);
    int   oix = __shfl_xor_sync(FULLMASK, idx, m);
    if (omx > mx || (omx == mx && oix < idx)){ mx = omx; idx = oix; }
  }
}

// ---------------- warp bitonic sort of 256 floats (8 regs/lane, idx i = lane*8 + r) ----------------
__device__ __forceinline__ void ce(float &a, float &b, bool up){
  float mn = fminf(a,b), mx = fmaxf(a,b);
  a = up ? mn : mx;  b = up ? mx : mn;
}
__device__ __forceinline__ void ce_shfl(float v[8], int jl, bool up, int lane){
  bool keepmin = (((lane & jl) == 0) == up);
#pragma unroll
  for (int r = 0; r < 8; r++){
    float o = __shfl_xor_sync(FULLMASK, v[r], jl);
    float mn = fminf(v[r], o), mx = fmaxf(v[r], o);
    v[r] = keepmin ? mn : mx;
  }
}
__device__ __forceinline__ void merge8(float v[8], bool up){
  ce(v[0],v[4],up); ce(v[1],v[5],up); ce(v[2],v[6],up); ce(v[3],v[7],up);
  ce(v[0],v[2],up); ce(v[1],v[3],up); ce(v[4],v[6],up); ce(v[5],v[7],up);
  ce(v[0],v[1],up); ce(v[2],v[3],up); ce(v[4],v[5],up); ce(v[6],v[7],up);
}
__device__ __forceinline__ void sort256(float v[8], int lane){
  ce(v[0],v[1],true);  ce(v[2],v[3],false); ce(v[4],v[5],true);  ce(v[6],v[7],false);
  ce(v[0],v[2],true);  ce(v[1],v[3],true);  ce(v[4],v[6],false); ce(v[5],v[7],false);
  ce(v[0],v[1],true);  ce(v[2],v[3],true);  ce(v[4],v[5],false); ce(v[6],v[7],false);
  { bool up = ((lane & 1) == 0); merge8(v, up); }
  { bool up = ((lane & 2) == 0); ce_shfl(v,1,up,lane); merge8(v, up); }
  { bool up = ((lane & 4) == 0); ce_shfl(v,2,up,lane); ce_shfl(v,1,up,lane); merge8(v, up); }
  { bool up = ((lane & 8) == 0); ce_shfl(v,4,up,lane); ce_shfl(v,2,up,lane); ce_shfl(v,1,up,lane); merge8(v, up); }
  { bool up = ((lane & 16) == 0); ce_shfl(v,8,up,lane); ce_shfl(v,4,up,lane); ce_shfl(v,2,up,lane); ce_shfl(v,1,up,lane); merge8(v, up); }
  { ce_shfl(v,16,true,lane); ce_shfl(v,8,true,lane); ce_shfl(v,4,true,lane); ce_shfl(v,2,true,lane); ce_shfl(v,1,true,lane); merge8(v, true); }
}
template<int G> __device__ __forceinline__ float rank_of(const float v[8]){
  return __shfl_sync(FULLMASK, v[G & 7], G >> 3);
}

// ---------------- summary stats (8 features) for a nonnegative signal in regs ----------------
__device__ void do_summary(float n[8], float *featbase, int lane){
  float s = 0.f, s2 = 0.f, mx = 0.f;
#pragma unroll
  for (int r = 0; r < 8; r++){ s += n[r]; s2 += n[r]*n[r]; mx = fmaxf(mx, n[r]); }
  s  = wredsum(s); s2 = wredsum(s2); mx = wredmax(mx);
  float mean = s * (1.f/256.f);
  float m2 = 0.f, m3 = 0.f, m4 = 0.f;
#pragma unroll
  for (int r = 0; r < 8; r++){
    float c = n[r] - mean; float c2 = c*c;
    m2 += c2; m3 += c2*c; m4 += c2*c2;
  }
  m2 = wredsum(m2); m3 = wredsum(m3); m4 = wredsum(m4);
  sort256(n, lane);
  float s63  = rank_of<63>(n),  s64  = rank_of<64>(n);
  float s191 = rank_of<191>(n), s192 = rank_of<192>(n);
  float s242 = rank_of<242>(n), s243 = rank_of<243>(n);
  float q25 = 0.25f*s63 + 0.75f*s64;
  float q75 = 0.75f*s191 + 0.25f*s192;
  float q95 = 0.75f*s242 + 0.25f*s243;
  float var = fmaxf(m2 * (1.f/256.f), EPSV);
  float stdv = fsqrt_a(m2 * (1.f/255.f));
  float rms  = fsqrt_a(s2 * (1.f/256.f));
  float iv   = frcp_a(var);
  float skew = fminf(fmaxf((m3 * (1.f/256.f)) * iv * frcp_a(fsqrt_a(var)), -10.f), 10.f);
  float kurt = fminf(fmaxf((m4 * (1.f/256.f)) * iv * iv, 0.f), 30.f);
  if (lane == 0){
    featbase[0] = mean; featbase[1] = stdv; featbase[2] = rms; featbase[3] = mx;
    featbase[4] = q95;  featbase[5] = q75 - q25; featbase[6] = skew; featbase[7] = kurt;
  }
}

// ---------------- phase features ----------------
__device__ void do_phase(const float *z, int off, int sT, int R, float *feat6, int lane){
  float mx = -1.f; int idx = 1 << 30;
  for (int t = lane; t < sT; t += 32){
    float v = fabsf(z[off + t]);
    if (v > mx){ mx = v; idx = t; }     // strict > keeps first occurrence within lane
  }
  wredmaxidx(mx, idx);
  float pk = mx;
  int W = 2*R + 1;
  float ssum = 0.f, spre = 0.f, spost = 0.f, cnt = 0.f;
  for (int j = lane; j < W; j += 32){
    int u = idx + j - R; u = max(0, min(u, sT - 1));
    float loc = fabsf(z[off + u]);
    ssum += loc;
    if (j < R) spre += loc;
    if (j > R) spost += loc;
    if (loc >= 0.2f * pk) cnt += 1.f;
  }
  ssum = wredsum(ssum); spre = wredsum(spre); spost = wredsum(spost); cnt = wredsum(cnt);
  float mj = 0.f, sj2 = 0.f;
  for (int t = lane; t < sT - 1; t += 32){
    float d = z[off + t + 1] - z[off + t];
    mj = fmaxf(mj, fabsf(d)); sj2 += d*d;
  }
  mj = wredmax(mj); sj2 = wredsum(sj2);
  if (lane == 0){
    feat6[0] = pk;
    feat6[1] = ssum;
    feat6[2] = (spost / (float)R) / ((spre / (float)R) + EPSV);
    feat6[3] = cnt / (float)W;
    feat6[4] = mj;
    feat6[5] = fsqrt_a(sj2 / (float)(sT - 1));
  }
}

// ---------------- spectral features from power[0..128] ----------------
__device__ void do_spectral(const float *pw, float *feat7, int lane){
  float tot=0.f, b0=0.f, b1=0.f, b2=0.f, b3=0.f, b4=0.f;
  for (int k = lane; k <= 128; k += 32){
    float p = pw[k]; tot += p;
    if (k < 8) b0 += p; else if (k < 16) b1 += p; else if (k < 26) b2 += p;
    else if (k < 52) b3 += p; else if (k < 103) b4 += p;
  }
  tot = wredsum(tot); b0 = wredsum(b0); b1 = wredsum(b1);
  b2 = wredsum(b2);  b3 = wredsum(b3); b4 = wredsum(b4);
  tot = fmaxf(tot, 1e-8f);
  float inv = frcp_a(tot);
  float ent = 0.f;
  for (int k = lane; k <= 128; k += 32){
    float p = fmaxf(pw[k] * inv, 1e-8f);
    ent += p * __logf(p);
  }
  ent = wredsum(ent);
  float carry = 0.f; int found = 200;
  for (int c = 0; c < 5; c++){
    int k = c*32 + lane;
    float p = (k <= 128) ? fmaxf(pw[k] * inv, 1e-8f) : 0.f;
    float s = p;
#pragma unroll
    for (int o = 1; o < 32; o <<= 1){
      float u = __shfl_up_sync(FULLMASK, s, o);
      if (lane >= o) s += u;
    }
    float cum = carry + s;
    bool pred = (k <= 128) && (cum >= 0.85f);
    unsigned mball = __ballot_sync(FULLMASK, pred);
    if (mball && found == 200) found = c*32 + __ffs(mball) - 1;
    carry += __shfl_sync(FULLMASK, s, 31);
  }
  int eidx = (found == 200) ? 0 : found;
  if (lane == 0){
    feat7[0] = b0*inv; feat7[1] = b1*inv; feat7[2] = b2*inv; feat7[3] = b3*inv; feat7[4] = b4*inv;
    feat7[5] = -ent / 4.867534450455582f;   // log(130)
    feat7[6] = (float)eidx * 0.390625f;     // k * 100/256
  }
}

// ---------------- time-domain normalized xcorr, lags -8..8 (register-cached windows) ------
// zx/zy point into padded Z (8 valid floats exist before and after each 1024 block)
__device__ void do_xcorr(const float *zx, const float *zy, float &mv, float &lag, int lane){
  int t0 = lane*8;
  float xv[8], yo[8];
  { const float4 *p = reinterpret_cast<const float4*>(zx + t0);
    float4 a = p[0], b = p[1];
    xv[0]=a.x; xv[1]=a.y; xv[2]=a.z; xv[3]=a.w; xv[4]=b.x; xv[5]=b.y; xv[6]=b.z; xv[7]=b.w; }
  { const float4 *p = reinterpret_cast<const float4*>(zy + t0);
    float4 a = p[0], b = p[1];
    yo[0]=a.x; yo[1]=a.y; yo[2]=a.z; yo[3]=a.w; yo[4]=b.x; yo[5]=b.y; yo[6]=b.z; yo[7]=b.w; }
  float sx = 0.f, sy = 0.f;
#pragma unroll
  for (int r = 0; r < 8; r++){ sx += xv[r]; sy += yo[r]; }
  sx = wredsum(sx) * (1.f/256.f); sy = wredsum(sy) * (1.f/256.f);
  float sx2 = 0.f, sy2 = 0.f;
#pragma unroll
  for (int r = 0; r < 8; r++){
    xv[r] -= sx; sx2 += xv[r]*xv[r];
    float y0 = yo[r] - sy; sy2 += y0*y0;
  }
  sx2 = wredsum(sx2); sy2 = wredsum(sy2);
  float g[17];
#pragma unroll
  for (int j = 0; j < 17; j++) g[j] = 0.f;
  // group A: lags m=0..8 need y0[t0 .. t0+15]
  {
    float w[16];
    const float4 *p = reinterpret_cast<const float4*>(zy + t0);
#pragma unroll
    for (int q = 0; q < 4; q++){
      float4 v = p[q];
      int ub = t0 + q*4;
      w[q*4+0] = (ub+0 < 256) ? v.x - sy : 0.f;
      w[q*4+1] = (ub+1 < 256) ? v.y - sy : 0.f;
      w[q*4+2] = (ub+2 < 256) ? v.z - sy : 0.f;
      w[q*4+3] = (ub+3 < 256) ? v.w - sy : 0.f;
    }
#pragma unroll
    for (int r = 0; r < 8; r++)
#pragma unroll
      for (int m = 0; m <= 8; m++)
        g[m] += xv[r] * w[r + 8 - m];
  }
  // group B: lags m=9..16 need y0[t0-8 .. t0+7]
  {
    float w[16];
    const float4 *p = reinterpret_cast<const float4*>(zy + t0 - 8);
#pragma unroll
    for (int q = 0; q < 4; q++){
      float4 v = p[q];
      int ub = t0 - 8 + q*4;
      w[q*4+0] = (ub+0 >= 0) ? v.x - sy : 0.f;
      w[q*4+1] = (ub+1 >= 0) ? v.y - sy : 0.f;
      w[q*4+2] = (ub+2 >= 0) ? v.z - sy : 0.f;
      w[q*4+3] = (ub+3 >= 0) ? v.w - sy : 0.f;
    }
#pragma unroll
    for (int r = 0; r < 8; r++)
#pragma unroll
      for (int m = 9; m <= 16; m++)
        g[m] += xv[r] * w[r + 16 - m];
  }
#pragma unroll
  for (int j = 0; j < 17; j++) g[j] = wredsum(g[j]);
  float rd = frcp_a(fsqrt_a(sx2) * fsqrt_a(sy2) + EPSV);
  float best = -1e30f; int bi = 0;
#pragma unroll
  for (int j = 0; j < 17; j++){
    float v = g[j] * rd;
    if (v > best){ best = v; bi = j; }
  }
  mv = best; lag = (float)(bi - 8);
}

// ---------------- register warp FFT-256 (DIF; 8 complex/lane at e = r*32 + lane) ----------
__device__ __forceinline__ void bfly(float &ar, float &ai, float &br, float &bi, float wr, float wi){
  float sr = ar + br, si = ai + bi;
  float dr = ar - br, di = ai - bi;
  ar = sr; ai = si;
  br = dr*wr - di*wi;
  bi = dr*wi + di*wr;
}
template<int M>
__device__ __forceinline__ void xstage(float cr[8], float ci[8], float wr, float wi, int lane){
  bool hi = (lane & M) != 0;
#pragma unroll
  for (int r = 0; r < 8; r++){
    float ore = __shfl_xor_sync(FULLMASK, cr[r], M);
    float oim = __shfl_xor_sync(FULLMASK, ci[r], M);
    float sre = cr[r] + ore, sim = ci[r] + oim;
    float dre = ore - cr[r], dim = oim - ci[r];   // (a - b) for hi lane (a = partner)
    float tre = dre*wr - dim*wi;
    float tim = dre*wi + dim*wr;
    cr[r] = hi ? tre : sre;
    ci[r] = hi ? tim : sim;
  }
}
// Runs the full FFT; input read from zre/zim (natural order), output stored to
// scratch (float2, natural frequency order; bit-reversal folded into store index).
__device__ void fft256_reg(const float *zre, const float *zim, float2 *scratch,
                           const float2 *tw2, int lane){
  float cr[8], ci[8];
#pragma unroll
  for (int r = 0; r < 8; r++){ cr[r] = zre[r*32 + lane]; ci[r] = zim[r*32 + lane]; }
  // stage half=128 (pairs r, r+4), tw idx = r*32+lane
#pragma unroll
  for (int r = 0; r < 4; r++){
    float2 w = tw2[r*32 + lane];
    bfly(cr[r], ci[r], cr[r+4], ci[r+4], w.x, w.y);
  }
  // stage half=64 (pairs (0,2),(1,3),(4,6),(5,7)), tw idx = ((r&1)*32+lane)*2
  {
    float2 w0 = tw2[(lane)*2];
    float2 w1 = tw2[(32 + lane)*2];
    bfly(cr[0], ci[0], cr[2], ci[2], w0.x, w0.y);
    bfly(cr[1], ci[1], cr[3], ci[3], w1.x, w1.y);
    bfly(cr[4], ci[4], cr[6], ci[6], w0.x, w0.y);
    bfly(cr[5], ci[5], cr[7], ci[7], w1.x, w1.y);
  }
  // stage half=32 (pairs (r, r+1) even r), tw idx = lane*4
  {
    float2 w = tw2[lane*4];
    bfly(cr[0], ci[0], cr[1], ci[1], w.x, w.y);
    bfly(cr[2], ci[2], cr[3], ci[3], w.x, w.y);
    bfly(cr[4], ci[4], cr[5], ci[5], w.x, w.y);
    bfly(cr[6], ci[6], cr[7], ci[7], w.x, w.y);
  }
  // cross-lane stages
  { float2 w = tw2[(lane & 15) * 8];  xstage<16>(cr, ci, w.x, w.y, lane); }
  { float2 w = tw2[(lane & 7) * 16];  xstage<8>(cr, ci, w.x, w.y, lane); }
  { float2 w = tw2[(lane & 3) * 32];  xstage<4>(cr, ci, w.x, w.y, lane); }
  { float2 w = tw2[(lane & 1) * 64];  xstage<2>(cr, ci, w.x, w.y, lane); }
  // last stage: w = 1
  {
    bool hi = (lane & 1) != 0;
#pragma unroll
    for (int r = 0; r < 8; r++){
      float ore = __shfl_xor_sync(FULLMASK, cr[r], 1);
      float oim = __shfl_xor_sync(FULLMASK, ci[r], 1);
      float sre = cr[r] + ore, sim = ci[r] + oim;
      float dre = ore - cr[r], dim = oim - ci[r];
      cr[r] = hi ? dre : sre;
      ci[r] = hi ? dim : sim;
    }
  }
  // store: slot e = r*32+lane holds X[bitrev8(e)]; write to natural index
  unsigned brl = __brev((unsigned)lane) >> 27;      // bitrev5(lane)
  const int br3[8] = {0,4,2,6,1,5,3,7};
#pragma unroll
  for (int r = 0; r < 8; r++){
    int k = (int)brl * 8 + br3[r];
    scratch[k] = make_float2(cr[r], ci[r]);
  }
  __syncwarp();
}

__device__ __forceinline__ void load8(const float *rowbase, int lane, float v[8]){
  const float4 *p = reinterpret_cast<const float4*>(rowbase) + lane*2;
  float4 a = p[0], b = p[1];
  v[0]=a.x; v[1]=a.y; v[2]=a.z; v[3]=a.w; v[4]=b.x; v[5]=b.y; v[6]=b.z; v[7]=b.w;
}

__global__ void __launch_bounds__(WPC*32)
terrain_kernel(const float* __restrict__ foot, const float* __restrict__ shank,
               const float* __restrict__ thigh, float* __restrict__ out, int B)
{
  __shared__ float2 tw2[128];
  __shared__ __align__(16) float zsh_s[WPC][4*256 + 16];  // padded: Z = base+8, valid [-8, 1031]
  __shared__ float2 fs_s[WPC][256];          // FFT output scratch
  __shared__ float pw_s[WPC][4*132];
  __shared__ __align__(16) float feat_s[WPC][224];
  __shared__ float wz_s[WPC][4];

  int tid = threadIdx.x;
  if (tid < 128){
    float sv, cv;
    sincosf((float)(-2.0 * M_PI / 256.0) * (float)tid, &sv, &cv);
    tw2[tid] = make_float2(cv, sv);
  }
  __syncthreads();

  int lane = tid & 31, w = tid >> 5;
  int b = blockIdx.x * WPC + w;
  if (b >= B) return;

  float *Z     = zsh_s[w] + 8;
  float2 *SCR  = fs_s[w];
  float *PW    = pw_s[w];
  float *FEAT  = feat_s[w];
  float *WZ    = wz_s[w];

  const float *F  = foot  + (size_t)b * 3072;
  const float *S  = shank + (size_t)b * 3072;
  const float *TH = thigh + (size_t)b * 3072;

  const int chmap[4] = {0, 6, 3, 9};   // a_lt, a_rt, g_lt, g_rt

  // ---- 12 norm signals: summary stats + z staging + horizontal blocks ----
  for (int s = 0; s < 12; s++){
    const float *base = (s < 4) ? F : (s < 8) ? S : TH;
    const float *row = base + chmap[s & 3] * 256;
    float x0[8], x1[8], x2[8];
    load8(row,        lane, x0);
    load8(row + 256,  lane, x1);
    load8(row + 512,  lane, x2);

    if (s == 0 || s == 1 || s == 4 || s == 5){
      int zi = (s < 2) ? s : (s - 2);
#pragma unroll
      for (int r = 0; r < 8; r++) Z[zi*256 + lane*8 + r] = x2[r];
      float zm = 0.f;
#pragma unroll
      for (int r = 0; r < 8; r++) zm = fmaxf(zm, fabsf(x2[r]));
      zm = wredmax(zm);
      if (lane == 0) WZ[zi] = zm;
    }

    if (s == 0 || s == 1){
      float h[8];
#pragma unroll
      for (int r = 0; r < 8; r++) h[r] = fsqrt_a(x0[r]*x0[r] + x1[r]*x1[r]);
      float sh2 = 0.f, hmax = 0.f, absz = 0.f;
#pragma unroll
      for (int r = 0; r < 8; r++){ sh2 += h[r]*h[r]; hmax = fmaxf(hmax, h[r]); absz += fabsf(x2[r]); }
      sh2 = wredsum(sh2); hmax = wredmax(hmax); absz = wredsum(absz);
      float h0n = __shfl_down_sync(FULLMASK, h[0], 1);
      float mj = 0.f, sj2 = 0.f;
#pragma unroll
      for (int r = 0; r < 8; r++){
        float nxt = (r < 7) ? h[r+1] : h0n;
        bool valid = (lane*8 + r) < 255;
        float d = nxt - h[r];
        if (valid){ mj = fmaxf(mj, fabsf(d)); sj2 += d*d; }
      }
      mj = wredmax(mj); sj2 = wredsum(sj2);
      sort256(h, lane);
      float q95h = 0.75f * rank_of<242>(h) + 0.25f * rank_of<243>(h);
      float rmsh  = fsqrt_a(sh2 * (1.f/256.f));
      float meanz = absz * (1.f/256.f);
      if (lane == 0){
        float *fb = FEAT + 184 + s*6;
        fb[0] = rmsh; fb[1] = hmax; fb[2] = q95h;
        fb[3] = mj;   fb[4] = fsqrt_a(sj2 * (1.f/255.f));
        fb[5] = rmsh / (meanz + EPSV);
      }
    }

    float n[8];
#pragma unroll
    for (int r = 0; r < 8; r++) n[r] = fsqrt_a(x0[r]*x0[r] + x1[r]*x1[r] + x2[r]*x2[r]);
    do_summary(n, FEAT + s*8, lane);
  }
  __syncwarp();

  // ---- spectral: 2 register FFTs serve 4 real z signals ----
  for (int f = 0; f < 2; f++){
    fft256_reg(Z + (2*f + 0)*256, Z + (2*f + 1)*256, SCR, tw2, lane);
    for (int k = lane; k <= 128; k += 32){
      int kk = (256 - k) & 255;
      float2 zk = SCR[k], zn = SCR[kk];
      float a = zk.x, bb = zk.y, c = zn.x, d = zn.y;
      float xr = 0.5f*(a + c),  xi = 0.5f*(bb - d);
      float yr = 0.5f*(bb + d), yi = 0.5f*(c - a);
      PW[(2*f + 0)*132 + k] = xr*xr + xi*xi;
      PW[(2*f + 1)*132 + k] = yr*yr + yi*yi;
    }
    __syncwarp();
  }
  for (int z = 0; z < 4; z++)
    do_spectral(PW + z*132, FEAT + 96 + z*7, lane);

  // ---- phase features: heel + toe per z ----
  for (int z = 0; z < 4; z++){
    do_phase(Z + z*256, 0,   115, 19, FEAT + 124 + z*6, lane);
    do_phase(Z + z*256, 153, 103, 17, FEAT + 148 + z*6, lane);
  }

  // ---- per-side blocks (xcorr + ratios) ----
  for (int side = 0; side < 2; side++){
    int fi = side, si = side + 2;
    float mv, lagv;
    do_xcorr(Z + fi*256, Z + si*256, mv, lagv, lane);
    if (lane == 0){
      float ratio = FEAT[(4 + side)*8 + 2] / (FEAT[side*8 + 2] + EPSV);
      float *fb = FEAT + 172 + side*6;
      fb[0] = WZ[si] / (WZ[fi] + EPSV);
      fb[1] = ratio;
      fb[2] = FEAT[124 + si*6 + 1] / (FEAT[124 + fi*6 + 1] + EPSV);
      fb[3] = mv;
      fb[4] = lagv;
      fb[5] = 0.5f * (FEAT[96 + si*7 + 4] / (FEAT[96 + fi*7 + 4] + EPSV) + (1.f - ratio));
    }
  }

  // ---- asymmetry block ----
  if (lane == 0){
    float *fb = FEAT + 196;
    #define ASYM(a_, b_) fabsf(logf(((a_) + EPSV) / ((b_) + EPSV)))
    fb[0]  = ASYM(FEAT[0*8+3],  FEAT[1*8+3]);
    fb[1]  = ASYM(FEAT[0*8+2],  FEAT[1*8+2]);
    fb[2]  = ASYM(FEAT[2*8+3],  FEAT[3*8+3]);
    fb[3]  = ASYM(FEAT[2*8+2],  FEAT[3*8+2]);
    fb[4]  = ASYM(FEAT[4*8+3],  FEAT[5*8+3]);
    fb[5]  = ASYM(FEAT[4*8+2],  FEAT[5*8+2]);
    fb[6]  = ASYM(FEAT[6*8+3],  FEAT[7*8+3]);
    fb[7]  = ASYM(FEAT[6*8+2],  FEAT[7*8+2]);
    fb[8]  = ASYM(FEAT[8*8+2],  FEAT[9*8+2]);
    fb[9]  = ASYM(FEAT[10*8+2], FEAT[11*8+2]);
    fb[10] = ASYM(FEAT[124+0*6+1], FEAT[124+1*6+1]);
    fb[11] = ASYM(FEAT[124+2*6+1], FEAT[124+3*6+1]);
    #undef ASYM
  }
  __syncwarp();

  // ---- write 208 features for this batch (vectorized: 52 float4 stores) ----
  {
    float4 *ob4 = reinterpret_cast<float4*>(out + (size_t)b * 208);
    const float4 *fb4 = reinterpret_cast<const float4*>(FEAT);
    for (int i = lane; i < 52; i += 32) ob4[i] = fb4[i];
  }
}

extern "C" void kernel_launch(void* const* d_in, const int* in_sizes, int n_in,
                              void* d_out, int out_size) {
  const float* foot  = (const float*)d_in[0];
  const float* shank = (const float*)d_in[1];
  const float* thigh = (const float*)d_in[2];
  float* out = (float*)d_out;
  int B = in_sizes[0] / (12 * 256);
  int ctas = (B + WPC - 1) / WPC;
  terrain_kernel<<<ctas, WPC*32>>>(foot, shank, thigh, out, B);
}